// round 16
// baseline (speedup 1.0000x reference)
#include <cuda_runtime.h>
#include <cstdint>

// ---------------- problem constants ----------------
constexpr int P_   = 64;
constexpr int NV2  = 32 * 64 * 64;        // comb2 voxels / channel stride
constexpr int C1STRIDE = 64 * 128 * 128;  // out1 channel stride
constexpr int V4 = 1728;                  // 12^3
constexpr int Vc = 13824;                 // 24^3
constexpr int NB2 = 108;                  // back2 n-tiles per proposal (13824/128)
constexpr int WSS = 66;                   // Ws row stride (rpn/conv_low)
constexpr float EPSN = 1e-5f;

typedef unsigned long long u64;

// ---------------- scratch ----------------
__device__ float g_T[P_ * 64 * V4];
__device__ float g_U[(long long)P_ * 64 * Vc];     // normalized+relu'd U
__device__ float g_F[(long long)P_ * 64 * Vc];
__device__ float g_spS[P_ * NB2 * 64];
__device__ float g_spQ[P_ * NB2 * 64];
__device__ float g_CR[P_ * 64 * 512];
__device__ float g_X1p[16 * P_ * 512];

// ---------------- f32x2 helpers ----------------
__device__ __forceinline__ u64 ffma2(u64 a, u64 b, u64 c) {
    u64 d; asm("fma.rn.f32x2 %0, %1, %2, %3;" : "=l"(d) : "l"(a), "l"(b), "l"(c)); return d;
}
__device__ __forceinline__ u64 pk2(float x, float y) {
    u64 d; asm("mov.b64 %0, {%1, %2};" : "=l"(d) : "f"(x), "f"(y)); return d;
}
__device__ __forceinline__ float2 unpk2(u64 v) {
    float2 r; asm("mov.b64 {%0, %1}, %2;" : "=f"(r.x), "=f"(r.y) : "l"(v)); return r;
}

// ---------------- cp.async helpers ----------------
__device__ __forceinline__ void cpa16(uint32_t dst, const float* src) {
    asm volatile("cp.async.cg.shared.global [%0], [%1], 16;\n" :: "r"(dst), "l"(src));
}
__device__ __forceinline__ void cpa8(uint32_t dst, const float* src) {
    asm volatile("cp.async.ca.shared.global [%0], [%1], 8;\n" :: "r"(dst), "l"(src));
}
__device__ __forceinline__ void cpa4(uint32_t dst, const float* src) {
    asm volatile("cp.async.ca.shared.global [%0], [%1], 4;\n" :: "r"(dst), "l"(src));
}
__device__ __forceinline__ void cp_commit() {
    asm volatile("cp.async.commit_group;\n");
}
template<int N> __device__ __forceinline__ void cp_wait() {
    asm volatile("cp.async.wait_group %0;\n" :: "n"(N));
}
__device__ __forceinline__ void cp_wait_tail(int kc) {
    if (kc <= 5) cp_wait<2>();
    else if (kc == 6) cp_wait<1>();
    else cp_wait<0>();
}

// ---------------- tf32 helpers ----------------
__device__ __forceinline__ float totf32(float x) {
    float r; asm("cvt.rna.tf32.f32 %0, %1;" : "=f"(r) : "f"(x)); return r;
}
__device__ __forceinline__ void mma_tf32(float c[4], float a0, float a1, float a2, float a3,
                                         float b0, float b1) {
    asm volatile(
        "mma.sync.aligned.m16n8k8.row.col.f32.tf32.tf32.f32 "
        "{%0,%1,%2,%3}, {%4,%5,%6,%7}, {%8,%9}, {%0,%1,%2,%3};"
        : "+f"(c[0]), "+f"(c[1]), "+f"(c[2]), "+f"(c[3])
        : "r"(__float_as_uint(a0)), "r"(__float_as_uint(a1)),
          "r"(__float_as_uint(a2)), "r"(__float_as_uint(a3)),
          "r"(__float_as_uint(b0)), "r"(__float_as_uint(b1)));
}

// stage W[64][128] (global, m-major) -> Ws[128][WSS] (k-major, padded) — rpn/conv_low
__device__ __forceinline__ void stageW(float* Ws, const float* __restrict__ w, int tid) {
    int kg = (tid & 31) * 4;
    int mb = (tid >> 5) * 8;
#pragma unroll
    for (int mm = 0; mm < 8; mm++) {
        int m = mb + mm;
        float4 v = *(const float4*)(w + m * 128 + kg);
        Ws[(kg + 0) * WSS + m] = v.x;
        Ws[(kg + 1) * WSS + m] = v.y;
        Ws[(kg + 2) * WSS + m] = v.z;
        Ws[(kg + 3) * WSS + m] = v.w;
    }
}

// mainloop over one K=16 chunk (proven) — rpn/conv_low
__device__ __forceinline__ void mm16(const float* WsK, const float* Xs,
                                     int tm, int tn, u64 acc[4][8]) {
#pragma unroll
    for (int k = 0; k < 16; k++) {
        const float* wp = WsK + k * WSS + tm * 8;
        u64 a0 = *(const u64*)(wp);
        u64 a1 = *(const u64*)(wp + 2);
        u64 a2 = *(const u64*)(wp + 4);
        u64 a3 = *(const u64*)(wp + 6);
        float4 xl = *(const float4*)(Xs + k * 256 + tn * 4);
        float4 xh = *(const float4*)(Xs + k * 256 + 128 + tn * 4);
        u64 a[4] = {a0, a1, a2, a3};
        u64 b[8] = {pk2(xl.x, xl.x), pk2(xl.y, xl.y), pk2(xl.z, xl.z), pk2(xl.w, xl.w),
                    pk2(xh.x, xh.x), pk2(xh.y, xh.y), pk2(xh.z, xh.z), pk2(xh.w, xh.w)};
#pragma unroll
        for (int i = 0; i < 4; i++)
#pragma unroll
            for (int j = 0; j < 8; j++) acc[i][j] = ffma2(a[i], b[j], acc[i][j]);
    }
}

constexpr int XCH = 16 * 256;   // floats per chunk buffer (rpn/conv_low)

// ---------------- RPN: tiled conv 128->64 + fused heads (4-stage ring) ----------------
constexpr int RPN_FLOATS = 8448 + 4 * XCH + 1344 + 24 + 64;
constexpr int RPN_SMEM = RPN_FLOATS * 4;
__global__ __launch_bounds__(256, 2) void k_rpn2(
    const float* __restrict__ comb2,
    const float* __restrict__ w_rpn, const float* __restrict__ b_rpn,
    const float* __restrict__ w_rlog, const float* __restrict__ b_rlog,
    const float* __restrict__ w_rdel, const float* __restrict__ b_rdel,
    float* __restrict__ out)
{
    extern __shared__ float sm[];
    float* Ws  = sm;
    float* Xb  = sm + 8448;
    float* wc  = sm + 8448 + 4 * XCH;
    float* bc  = wc + 1344;
    float* sb  = bc + 24;
    float* Hs  = sm;
    int tid = threadIdx.x;
    int vox0 = blockIdx.x * 256;

    int tn = tid & 31, tm = tid >> 5;
    int c4 = tid & 63, rg = tid >> 6;
    uint32_t sX = (uint32_t)__cvta_generic_to_shared(Xb);

    auto stage = [&](int kc) {
        uint32_t sbuf = sX + (kc & 3) * XCH * 4;
#pragma unroll
        for (int rr = 0; rr < 4; rr++) {
            int row = rg * 4 + rr;
            cpa16(sbuf + (row * 256 + c4 * 4) * 4,
                  comb2 + (long long)(kc * 16 + row) * NV2 + vox0 + c4 * 4);
        }
        cp_commit();
    };

    stage(0); stage(1); stage(2);

    stageW(Ws, w_rpn, tid);
    for (int i = tid; i < 64 * 21; i += 256) {
        int o = i / 21, t = i - o * 21;
        wc[i] = (t < 3) ? w_rlog[t * 64 + o] : w_rdel[(t - 3) * 64 + o];
    }
    if (tid < 21) bc[tid] = (tid < 3) ? b_rlog[tid] : b_rdel[tid - 3];
    if (tid < 64) sb[tid] = b_rpn[tid];
    __syncthreads();

    u64 acc[4][8];
#pragma unroll
    for (int i = 0; i < 4; i++) { int m = tm * 8 + 2 * i;
#pragma unroll
        for (int j = 0; j < 8; j++) acc[i][j] = pk2(sb[m], sb[m + 1]); }

#pragma unroll 1
    for (int kc = 0; kc < 8; kc++) {
        cp_wait_tail(kc);
        __syncthreads();
        if (kc + 3 < 8) stage(kc + 3);
        mm16(Ws + kc * 16 * WSS, Xb + (kc & 3) * XCH, tm, tn, acc);
    }
    __syncthreads();

#pragma unroll
    for (int i = 0; i < 4; i++) {
        int m = tm * 8 + 2 * i;
#pragma unroll
        for (int h = 0; h < 2; h++) {
            float2 v0 = unpk2(acc[i][h * 4 + 0]), v1 = unpk2(acc[i][h * 4 + 1]);
            float2 v2 = unpk2(acc[i][h * 4 + 2]), v3 = unpk2(acc[i][h * 4 + 3]);
            *(float4*)&Hs[m * 256 + h * 128 + tn * 4] =
                make_float4(fmaxf(v0.x, 0.f), fmaxf(v1.x, 0.f), fmaxf(v2.x, 0.f), fmaxf(v3.x, 0.f));
            *(float4*)&Hs[(m + 1) * 256 + h * 128 + tn * 4] =
                make_float4(fmaxf(v0.y, 0.f), fmaxf(v1.y, 0.f), fmaxf(v2.y, 0.f), fmaxf(v3.y, 0.f));
        }
    }
    __syncthreads();

    int vx = tid;
    float a[21];
#pragma unroll
    for (int t = 0; t < 21; t++) a[t] = bc[t];
    for (int o = 0; o < 64; o++) {
        float h = Hs[o * 256 + vx];
#pragma unroll
        for (int t = 0; t < 21; t++) a[t] = fmaf(wc[o * 21 + t], h, a[t]);
    }
    long long vox = vox0 + vx;
#pragma unroll
    for (int t = 0; t < 3; t++) out[vox * 3 + t] = a[t];
#pragma unroll
    for (int t = 0; t < 18; t++) out[(long long)NV2 * 3 + vox * 18 + t] = a[3 + t];
}

// ---------------- conv_low: up2 conv at 12^3 (4-stage ring, 4B cp.async) ----------------
constexpr int CL_FLOATS = 8448 + 4 * XCH + 64;
constexpr int CL_SMEM = CL_FLOATS * 4;
__global__ __launch_bounds__(256, 2) void k_conv_low2(
    const float* __restrict__ comb2, const int* __restrict__ props,
    const float* __restrict__ w_up2, const float* __restrict__ b_up2)
{
    extern __shared__ float sm[];
    float* Ws = sm; float* Xb = sm + 8448; float* sb = sm + 8448 + 4 * XCH;
    int tid = threadIdx.x;
    int p = blockIdx.y, n0 = blockIdx.x * 256;

    int tn = tid & 31, tm = tid >> 5;
    int c4 = tid & 63, rg = tid >> 6;
    int v4 = n0 + c4 * 4; if (v4 > V4 - 4) v4 = V4 - 4;
    int z0 = props[p * 7 + 1] >> 2, y0 = props[p * 7 + 2] >> 2, x0 = props[p * 7 + 3] >> 2;
    int d = v4 / 144; int r = v4 - d * 144; int hh = r / 12; int ww = r - hh * 12;
    long long base = (long long)(z0 + d) * 4096 + (y0 + hh) * 64 + (x0 + ww);
    uint32_t sX = (uint32_t)__cvta_generic_to_shared(Xb);

    auto stage = [&](int kc) {
        uint32_t sbuf = sX + (kc & 3) * XCH * 4;
#pragma unroll
        for (int rr = 0; rr < 4; rr++) {
            int row = rg * 4 + rr;
            const float* gp = comb2 + (long long)(kc * 16 + row) * NV2 + base;
            uint32_t ds = sbuf + (row * 256 + c4 * 4) * 4;
            cpa4(ds, gp); cpa4(ds + 4, gp + 1); cpa4(ds + 8, gp + 2); cpa4(ds + 12, gp + 3);
        }
        cp_commit();
    };

    stage(0); stage(1); stage(2);
    stageW(Ws, w_up2, tid);
    if (tid < 64) sb[tid] = b_up2[tid];
    __syncthreads();

    u64 acc[4][8];
#pragma unroll
    for (int i = 0; i < 4; i++) { int m = tm * 8 + 2 * i;
#pragma unroll
        for (int j = 0; j < 8; j++) acc[i][j] = pk2(sb[m], sb[m + 1]); }

#pragma unroll 1
    for (int kc = 0; kc < 8; kc++) {
        cp_wait_tail(kc);
        __syncthreads();
        if (kc + 3 < 8) stage(kc + 3);
        mm16(Ws + kc * 16 * WSS, Xb + (kc & 3) * XCH, tm, tn, acc);
    }

    float* Tb = g_T + (long long)(p * 64) * V4 + n0 + tn * 4;
#pragma unroll
    for (int i = 0; i < 4; i++) {
        int m = tm * 8 + 2 * i;
#pragma unroll
        for (int h = 0; h < 2; h++) {
            int n = n0 + h * 128 + tn * 4;
            if (n < V4) {
                float2 v0 = unpk2(acc[i][h * 4 + 0]), v1 = unpk2(acc[i][h * 4 + 1]);
                float2 v2 = unpk2(acc[i][h * 4 + 2]), v3 = unpk2(acc[i][h * 4 + 3]);
                *(float4*)(Tb + (long long)m * V4 + h * 128) = make_float4(v0.x, v1.x, v2.x, v3.x);
                *(float4*)(Tb + (long long)(m + 1) * V4 + h * 128) = make_float4(v0.y, v1.y, v2.y, v3.y);
            }
        }
    }
}

// ---------------- upsample 12->24 + instnorm + relu ----------------
__global__ __launch_bounds__(288) void k_upsample(
    const float* __restrict__ gam, const float* __restrict__ bet)
{
    int c = blockIdx.x, p = blockIdx.y;
    __shared__ float t[V4];
    __shared__ int   llo[24], lhi[24];
    __shared__ float lf[24];
    __shared__ float bs[9], bss[9];
    __shared__ float sA, sB;
    int tid = threadIdx.x;
    const float* tp = &g_T[(p * 64 + c) * V4];
    for (int i = tid; i < V4; i += 288) t[i] = tp[i];
    if (tid < 24) {
        int nd = tid * 11; int lo = nd / 23;
        llo[tid] = lo; lhi[tid] = min(lo + 1, 11);
        lf[tid] = (float)(nd - lo * 23) * (1.0f / 23.0f);
    }
    __syncthreads();

    float s = 0.f, ss = 0.f;
    float outv[2][24];
#pragma unroll
    for (int rep = 0; rep < 2; rep++) {
        int rrow = tid + rep * 288;
        int d = rrow / 24; int h = rrow - d * 24;
        int ld = llo[d], hd = lhi[d]; float fd = lf[d];
        int lh = llo[h], hh = lhi[h]; float fh = lf[h];
        const float* p00 = t + ld * 144 + lh * 12;
        const float* p01 = t + ld * 144 + hh * 12;
        const float* p10 = t + hd * 144 + lh * 12;
        const float* p11 = t + hd * 144 + hh * 12;
        float rowc[12];
#pragma unroll
        for (int i = 0; i < 12; i++) {
            float a0 = p00[i], a1 = p01[i], b0 = p10[i], b1 = p11[i];
            float a = a0 + (a1 - a0) * fh;
            float b = b0 + (b1 - b0) * fh;
            rowc[i] = a + (b - a) * fd;
        }
#pragma unroll
        for (int w = 0; w < 24; w++) {
            const int nw = w * 11;
            const int lw = nw / 23;
            const int hw = (lw + 1 < 11) ? lw + 1 : 11;
            const float fw = (float)(nw - lw * 23) * (1.0f / 23.0f);
            float v = rowc[lw] + (rowc[hw] - rowc[lw]) * fw;
            outv[rep][w] = v;
            s += v; ss = fmaf(v, v, ss);
        }
    }

#pragma unroll
    for (int off = 16; off; off >>= 1) {
        s  += __shfl_down_sync(0xffffffffu, s,  off);
        ss += __shfl_down_sync(0xffffffffu, ss, off);
    }
    int wrp = tid >> 5, ln = tid & 31;
    if (ln == 0) { bs[wrp] = s; bss[wrp] = ss; }
    __syncthreads();
    if (wrp == 0 && ln < 9) {
        s = bs[ln]; ss = bss[ln];
#pragma unroll
        for (int off = 8; off; off >>= 1) {
            s  += __shfl_down_sync(0x1ffu, s,  off);
            ss += __shfl_down_sync(0x1ffu, ss, off);
        }
        if (ln == 0) {
            float mean = s * (1.f / Vc);
            float var = ss * (1.f / Vc) - mean * mean;
            float a = gam[c] * rsqrtf(var + EPSN);
            sA = a; sB = bet[c] - mean * a;
        }
    }
    __syncthreads();
    float a = sA, b = sB;

    float* up = &g_U[((long long)(p * 64 + c)) * Vc];
#pragma unroll
    for (int rep = 0; rep < 2; rep++) {
        int rrow = tid + rep * 288;
        float* o = up + rrow * 24;
#pragma unroll
        for (int q = 0; q < 6; q++) {
            float v0 = fmaxf(fmaf(outv[rep][q*4+0], a, b), 0.f);
            float v1 = fmaxf(fmaf(outv[rep][q*4+1], a, b), 0.f);
            float v2 = fmaxf(fmaf(outv[rep][q*4+2], a, b), 0.f);
            float v3 = fmaxf(fmaf(outv[rep][q*4+3], a, b), 0.f);
            *(float4*)(o + q * 4) = make_float4(v0, v1, v2, v3);
        }
    }
}

// ---------------- back2: tf32 mma.sync GEMM, M64 x N128 per block ----------------
// A pre-packed in fragment order: Apk[kstep(16)][mwarp(4)][lane(32)][4] -> 1 LDS.128 / k8
// X ring with XST=136 (banks 8*tig+gid: conflict-free); B fed as raw f32 bits (HW tf32 trunc)
constexpr int APK = 16 * 4 * 32 * 4;    // 8192 floats
constexpr int XST = 136;                // X smem row stride
constexpr int XCB = 16 * XST;           // 2176 floats per k16 chunk
constexpr int B2_FLOATS = APK + 4 * XCB + 64 + 128;
constexpr int B2_SMEM = B2_FLOATS * 4;  // ~68 KB
__global__ __launch_bounds__(256) void k_back2m(
    const float* __restrict__ out1, const int* __restrict__ props,
    const float* __restrict__ w_back2, const float* __restrict__ b_back2)
{
    extern __shared__ float sm[];
    float* Apk   = sm;                       // 8192
    float* Xb    = sm + APK;                 // 4 ring chunks [16][XST]
    float* biasS = sm + APK + 4 * XCB;       // 64
    float* stS   = biasS + 64;               // [2][64]
    int tid = threadIdx.x;
    int lane = tid & 31, w = tid >> 5;
    int gid = lane >> 2, tig = lane & 3;
    int mwarp = w & 3, nw = (w >> 2) * 64;
    int mw = mwarp * 16;
    int p = blockIdx.y, n0 = blockIdx.x * 128;

    int tn = tid & 31, rg = tid >> 5;
    int v4 = n0 + tn * 4;
    int z0 = props[p * 7 + 1] >> 1, y0 = props[p * 7 + 2] >> 1, x0 = props[p * 7 + 3] >> 1;
    int d = v4 / 576; int r = v4 - d * 576; int hh = r / 24; int ww = r - hh * 24;
    long long o1b = ((long long)(z0 + d) * 128 + (y0 + hh)) * 128 + (x0 + ww);
    const float* Ub = g_U + ((long long)p * 64) * Vc + v4;
    uint32_t sX = (uint32_t)__cvta_generic_to_shared(Xb);

    auto stage = [&](int kc) {
        uint32_t sbuf = sX + (kc & 3) * XCB * 4;
        if (kc < 4) {
#pragma unroll
            for (int rr = 0; rr < 2; rr++) {
                int row = rg * 2 + rr;
                cpa16(sbuf + (row * XST + tn * 4) * 4, Ub + (long long)(kc * 16 + row) * Vc);
            }
        } else {
#pragma unroll
            for (int rr = 0; rr < 2; rr++) {
                int row = rg * 2 + rr;
                const float* gp = out1 + (long long)((kc - 4) * 16 + row) * C1STRIDE + o1b;
                uint32_t ds = sbuf + (row * XST + tn * 4) * 4;
                cpa8(ds, gp); cpa8(ds + 8, gp + 2);
            }
        }
        cp_commit();
    };

    stage(0); stage(1); stage(2);
    // stage A into fragment-packed layout (tf32 rna converted once)
    {
        int kg = (tid & 31) * 4;
        int mb = (tid >> 5) * 8;
#pragma unroll
        for (int mm = 0; mm < 8; mm++) {
            int m = mb + mm;
            float4 v = *(const float4*)(w_back2 + m * 128 + kg);
            float vv[4] = {v.x, v.y, v.z, v.w};
#pragma unroll
            for (int i = 0; i < 4; i++) {
                int k = kg + i;
                int s = k >> 3, kin = k & 7;
                int tg = kin & 3, sub = kin >> 2;
                int mw2 = m >> 4, mloc = m & 15;
                int j = sub * 2 + (mloc >> 3);
                int ln2 = (mloc & 7) * 4 + tg;
                Apk[((s * 4 + mw2) * 32 + ln2) * 4 + j] = totf32(vv[i]);
            }
        }
    }
    if (tid < 64) biasS[tid] = b_back2[tid];
    __syncthreads();

    float acc[8][4];
#pragma unroll
    for (int t = 0; t < 8; t++)
#pragma unroll
        for (int j = 0; j < 4; j++) acc[t][j] = 0.f;

#pragma unroll 1
    for (int kc = 0; kc < 8; kc++) {
        cp_wait_tail(kc);
        __syncthreads();
        if (kc + 3 < 8) stage(kc + 3);
        const float* Xc = Xb + (kc & 3) * XCB;
#pragma unroll
        for (int ks = 0; ks < 2; ks++) {
            int s = kc * 2 + ks;
            float4 av = *(const float4*)&Apk[((s * 4 + mwarp) * 32 + lane) * 4];
            const float* xk = Xc + ks * 8 * XST + nw + gid;
#pragma unroll
            for (int t = 0; t < 8; t++) {
                float b0 = xk[tig * XST + t * 8];
                float b1 = xk[(tig + 4) * XST + t * 8];
                mma_tf32(acc[t], av.x, av.y, av.z, av.w, b0, b1);
            }
        }
    }

    // epilogue: bias + store F (float2, cols tig*2) + per-row stats
    int r0 = mw + gid, r1 = mw + gid + 8;
    float bias0 = biasS[r0], bias1 = biasS[r1];
    float S0 = 0.f, Q0 = 0.f, S1 = 0.f, Q1 = 0.f;
    float* F0 = g_F + ((long long)(p * 64 + r0)) * Vc + n0 + nw + tig * 2;
    float* F1 = g_F + ((long long)(p * 64 + r1)) * Vc + n0 + nw + tig * 2;
#pragma unroll
    for (int t = 0; t < 8; t++) {
        float v00 = acc[t][0] + bias0, v01 = acc[t][1] + bias0;
        float v10 = acc[t][2] + bias1, v11 = acc[t][3] + bias1;
        *(float2*)(F0 + t * 8) = make_float2(v00, v01);
        *(float2*)(F1 + t * 8) = make_float2(v10, v11);
        S0 += v00 + v01; Q0 = fmaf(v00, v00, Q0); Q0 = fmaf(v01, v01, Q0);
        S1 += v10 + v11; Q1 = fmaf(v10, v10, Q1); Q1 = fmaf(v11, v11, Q1);
    }
#pragma unroll
    for (int off = 2; off; off >>= 1) {
        S0 += __shfl_down_sync(0xffffffffu, S0, off, 4);
        Q0 += __shfl_down_sync(0xffffffffu, Q0, off, 4);
        S1 += __shfl_down_sync(0xffffffffu, S1, off, 4);
        Q1 += __shfl_down_sync(0xffffffffu, Q1, off, 4);
    }
    if (tig == 0) {
        int half = w >> 2;
        stS[half * 64 + r0] = S0;  stS[half * 64 + r1] = S1;
    }
    __syncthreads();
    float sumv = 0.f;
    if (tid < 64) sumv = stS[tid] + stS[64 + tid];
    __syncthreads();
    if (tig == 0) {
        int half = w >> 2;
        stS[half * 64 + r0] = Q0;  stS[half * 64 + r1] = Q1;
    }
    __syncthreads();
    if (tid < 64) {
        int pbase = (p * NB2 + blockIdx.x) * 64;
        g_spS[pbase + tid] = sumv;
        g_spQ[pbase + tid] = stS[tid] + stS[64 + tid];
    }
}

// ---------------- normalize + relu + 3^3 maxpool (stats from partials) ----------------
__global__ __launch_bounds__(512) void k_pool(
    const float* __restrict__ gam, const float* __restrict__ bet)
{
    int o = blockIdx.x, p = blockIdx.y;
    __shared__ float sS, sQ;
    if (threadIdx.x < 32) {
        float S = 0.f, Q = 0.f;
        for (int b2 = threadIdx.x; b2 < NB2; b2 += 32) {
            S += g_spS[(p * NB2 + b2) * 64 + o];
            Q += g_spQ[(p * NB2 + b2) * 64 + o];
        }
#pragma unroll
        for (int off = 16; off; off >>= 1) {
            S += __shfl_down_sync(0xffffffffu, S, off);
            Q += __shfl_down_sync(0xffffffffu, Q, off);
        }
        if (threadIdx.x == 0) { sS = S; sQ = Q; }
    }
    __syncthreads();
    float mean = sS * (1.f / Vc);
    float var = sQ * (1.f / Vc) - mean * mean;
    float a = gam[o] * rsqrtf(var + EPSN);
    float b = bet[o] - mean * a;

    int j = threadIdx.x;
    int od = j >> 6; int r = j & 63; int oh = r >> 3; int ow = r & 7;
    const float* Fp = &g_F[((long long)(p * 64 + o)) * Vc];
    float m = -1e30f;
#pragma unroll
    for (int dz = 0; dz < 3; dz++)
#pragma unroll
        for (int dy = 0; dy < 3; dy++)
#pragma unroll
            for (int dx = 0; dx < 3; dx++) {
                float v = Fp[(od * 3 + dz) * 576 + (oh * 3 + dy) * 24 + (ow * 3 + dx)];
                m = fmaxf(m, fmaxf(fmaf(v, a, b), 0.f));
            }
    g_CR[(p * 64 + o) * 512 + j] = m;
}

// ---------------- fc1 GEMM (K-split, cp.async double-buffered) ----------------
constexpr int WS2 = 68;
constexpr int FC1_FLOATS = 2 * 64 * WS2 + 2 * 64 * 65;
constexpr int FC1_SMEM = FC1_FLOATS * 4;
__global__ __launch_bounds__(256) void k_fc1(const float* __restrict__ w_fc1)
{
    extern __shared__ float sm[];
    float* Wb0 = sm;
    float* Wb1 = sm + 64 * WS2;
    float* Xb0 = sm + 2 * 64 * WS2;
    float* Xb1 = Xb0 + 64 * 65;
    int tid = threadIdx.x;
    int m0 = blockIdx.x * 64;
    int kb = blockIdx.y;
    int tp = tid & 63, tm = tid >> 6;
    uint32_t sW0 = (uint32_t)__cvta_generic_to_shared(Wb0);
    uint32_t sW1 = (uint32_t)__cvta_generic_to_shared(Wb1);
    uint32_t sXb0 = (uint32_t)__cvta_generic_to_shared(Xb0);
    uint32_t sXb1 = (uint32_t)__cvta_generic_to_shared(Xb1);

    int wrow = tid >> 2, wc4 = tid & 3;

    auto stage = [&](int ch) {
        int buf = ch & 1;
        int k0 = kb * 2048 + ch * 64;
        const float* gw = w_fc1 + (long long)(m0 + wrow) * 32768 + k0 + wc4 * 16;
        uint32_t dw = (buf ? sW1 : sW0) + (wrow * WS2 + wc4 * 16) * 4;
        cpa16(dw, gw); cpa16(dw + 16, gw + 4); cpa16(dw + 32, gw + 8); cpa16(dw + 48, gw + 12);
        uint32_t sXd = buf ? sXb1 : sXb0;
#pragma unroll
        for (int it = 0; it < 16; it++) {
            int idx = tid + it * 256;
            int kk = idx & 63, row = idx >> 6;
            cpa4(sXd + (kk * 65 + row) * 4, g_CR + row * 32768 + k0 + kk);
        }
        cp_commit();
    };

    float acc[16];
#pragma unroll
    for (int i = 0; i < 16; i++) acc[i] = 0.f;

    stage(0);
#pragma unroll 1
    for (int ch = 0; ch < 32; ch++) {
        if (ch < 31) { stage(ch + 1); cp_wait<1>(); }
        else cp_wait<0>();
        __syncthreads();
        const float* Wsb = (ch & 1) ? Wb1 : Wb0;
        const float* Xsb = (ch & 1) ? Xb1 : Xb0;
#pragma unroll 8
        for (int k = 0; k < 64; k++) {
            float xv = Xsb[k * 65 + tp];
#pragma unroll
            for (int i = 0; i < 16; i++) acc[i] = fmaf(Wsb[(tm * 16 + i) * WS2 + k], xv, acc[i]);
        }
        __syncthreads();
    }
    float* outp = &g_X1p[((long long)kb * 64 + tp) * 512 + m0 + tm * 16];
#pragma unroll
    for (int i = 0; i < 16; i++) outp[i] = acc[i];
}

// ---------------- fc1 reduce + fc2 + relu + rcnn heads (fused) ----------------
__global__ __launch_bounds__(256) void k_fc2h(
    const float* __restrict__ b_fc1,
    const float* __restrict__ w_fc2, const float* __restrict__ b_fc2,
    const float* __restrict__ w_logit, const float* __restrict__ b_logit,
    const float* __restrict__ w_delta, const float* __restrict__ b_delta,
    float* __restrict__ out)
{
    int p = blockIdx.x; int o = threadIdx.x;
    __shared__ float xs[512];
    __shared__ float x2[256];
    for (int m = o; m < 512; m += 256) {
        float s = b_fc1[m];
#pragma unroll
        for (int kb = 0; kb < 16; kb++) s += g_X1p[((long long)kb * 64 + p) * 512 + m];
        xs[m] = fmaxf(s, 0.f);
    }
    __syncthreads();
    const float* wp = &w_fc2[o * 512];
    float s = b_fc2[o];
#pragma unroll 8
    for (int k = 0; k < 512; k++) s = fmaf(wp[k], xs[k], s);
    x2[o] = fmaxf(s, 0.f);
    __syncthreads();

    int w = o >> 5, ln = o & 31;
    const long long offL = (long long)NV2 * 21;
    for (int t = w; t < 14; t += 8) {
        const float* wt = (t < 2) ? &w_logit[t * 256] : &w_delta[(t - 2) * 256];
        float sv = 0.f;
        for (int k = ln; k < 256; k += 32) sv = fmaf(wt[k], x2[k], sv);
#pragma unroll
        for (int off = 16; off; off >>= 1) sv += __shfl_down_sync(0xffffffffu, sv, off);
        if (ln == 0) {
            if (t < 2) out[offL + p * 2 + t] = sv + b_logit[t];
            else       out[offL + 128 + p * 12 + (t - 2)] = sv + b_delta[t - 2];
        }
    }
}

// ---------------- launch ----------------
extern "C" void kernel_launch(void* const* d_in, const int* in_sizes, int n_in,
                              void* d_out, int out_size)
{
    const float* out1    = (const float*)d_in[0];
    const float* comb2   = (const float*)d_in[1];
    const int*   props   = (const int*)  d_in[2];
    const float* w_rpn   = (const float*)d_in[3];  const float* b_rpn   = (const float*)d_in[4];
    const float* w_rlog  = (const float*)d_in[5];  const float* b_rlog  = (const float*)d_in[6];
    const float* w_rdel  = (const float*)d_in[7];  const float* b_rdel  = (const float*)d_in[8];
    const float* w_up2   = (const float*)d_in[9];  const float* b_up2   = (const float*)d_in[10];
    const float* gu_up2  = (const float*)d_in[11]; const float* be_up2  = (const float*)d_in[12];
    const float* w_back2 = (const float*)d_in[13]; const float* b_back2 = (const float*)d_in[14];
    const float* gu_bk2  = (const float*)d_in[15]; const float* be_bk2  = (const float*)d_in[16];
    const float* w_fc1   = (const float*)d_in[17]; const float* b_fc1   = (const float*)d_in[18];
    const float* w_fc2   = (const float*)d_in[19]; const float* b_fc2   = (const float*)d_in[20];
    const float* w_logit = (const float*)d_in[21]; const float* b_logit = (const float*)d_in[22];
    const float* w_delta = (const float*)d_in[23]; const float* b_delta = (const float*)d_in[24];
    float* out = (float*)d_out;

    cudaFuncSetAttribute(k_rpn2, cudaFuncAttributeMaxDynamicSharedMemorySize, RPN_SMEM);
    cudaFuncSetAttribute(k_conv_low2, cudaFuncAttributeMaxDynamicSharedMemorySize, CL_SMEM);
    cudaFuncSetAttribute(k_back2m, cudaFuncAttributeMaxDynamicSharedMemorySize, B2_SMEM);
    cudaFuncSetAttribute(k_fc1, cudaFuncAttributeMaxDynamicSharedMemorySize, FC1_SMEM);

    k_rpn2<<<512, 256, RPN_SMEM>>>(comb2, w_rpn, b_rpn, w_rlog, b_rlog, w_rdel, b_rdel, out);
    k_conv_low2<<<dim3(7, P_), 256, CL_SMEM>>>(comb2, props, w_up2, b_up2);
    k_upsample<<<dim3(64, P_), 288>>>(gu_up2, be_up2);
    k_back2m<<<dim3(NB2, P_), 256, B2_SMEM>>>(out1, props, w_back2, b_back2);
    k_pool<<<dim3(64, P_), 512>>>(gu_bk2, be_bk2);
    k_fc1<<<dim3(8, 16), 256, FC1_SMEM>>>(w_fc1);
    k_fc2h<<<P_, 256>>>(b_fc1, w_fc2, b_fc2, w_logit, b_logit, w_delta, b_delta, out);
}

// round 17
// speedup vs baseline: 1.0385x; 1.0385x over previous
#include <cuda_runtime.h>
#include <cstdint>

// ---------------- problem constants ----------------
constexpr int P_   = 64;
constexpr int NV2  = 32 * 64 * 64;        // comb2 voxels / channel stride
constexpr int C1STRIDE = 64 * 128 * 128;  // out1 channel stride
constexpr int V4 = 1728;                  // 12^3
constexpr int Vc = 13824;                 // 24^3
constexpr int NB2 = 108;                  // back2 n-tiles per proposal (13824/128)
constexpr int WSS = 66;                   // Ws row stride (conv_low)
constexpr float EPSN = 1e-5f;

typedef unsigned long long u64;

// ---------------- scratch ----------------
__device__ float g_T[P_ * 64 * V4];
__device__ float g_U[(long long)P_ * 64 * Vc];     // normalized+relu'd U
__device__ float g_F[(long long)P_ * 64 * Vc];
__device__ float g_spS[P_ * NB2 * 64];
__device__ float g_spQ[P_ * NB2 * 64];
__device__ float g_CR[P_ * 64 * 512];
__device__ float g_X1p[16 * P_ * 512];

// ---------------- f32x2 helpers ----------------
__device__ __forceinline__ u64 ffma2(u64 a, u64 b, u64 c) {
    u64 d; asm("fma.rn.f32x2 %0, %1, %2, %3;" : "=l"(d) : "l"(a), "l"(b), "l"(c)); return d;
}
__device__ __forceinline__ u64 pk2(float x, float y) {
    u64 d; asm("mov.b64 %0, {%1, %2};" : "=l"(d) : "f"(x), "f"(y)); return d;
}
__device__ __forceinline__ float2 unpk2(u64 v) {
    float2 r; asm("mov.b64 {%0, %1}, %2;" : "=f"(r.x), "=f"(r.y) : "l"(v)); return r;
}

// ---------------- cp.async helpers ----------------
__device__ __forceinline__ void cpa16(uint32_t dst, const float* src) {
    asm volatile("cp.async.cg.shared.global [%0], [%1], 16;\n" :: "r"(dst), "l"(src));
}
__device__ __forceinline__ void cpa8(uint32_t dst, const float* src) {
    asm volatile("cp.async.ca.shared.global [%0], [%1], 8;\n" :: "r"(dst), "l"(src));
}
__device__ __forceinline__ void cpa4(uint32_t dst, const float* src) {
    asm volatile("cp.async.ca.shared.global [%0], [%1], 4;\n" :: "r"(dst), "l"(src));
}
__device__ __forceinline__ void cp_commit() {
    asm volatile("cp.async.commit_group;\n");
}
template<int N> __device__ __forceinline__ void cp_wait() {
    asm volatile("cp.async.wait_group %0;\n" :: "n"(N));
}
__device__ __forceinline__ void cp_wait_tail(int kc) {
    if (kc <= 5) cp_wait<2>();
    else if (kc == 6) cp_wait<1>();
    else cp_wait<0>();
}

// ---------------- tf32 helpers ----------------
__device__ __forceinline__ float totf32(float x) {
    float r; asm("cvt.rna.tf32.f32 %0, %1;" : "=f"(r) : "f"(x)); return r;
}
__device__ __forceinline__ void mma_tf32(float c[4], float a0, float a1, float a2, float a3,
                                         float b0, float b1) {
    asm volatile(
        "mma.sync.aligned.m16n8k8.row.col.f32.tf32.tf32.f32 "
        "{%0,%1,%2,%3}, {%4,%5,%6,%7}, {%8,%9}, {%0,%1,%2,%3};"
        : "+f"(c[0]), "+f"(c[1]), "+f"(c[2]), "+f"(c[3])
        : "r"(__float_as_uint(a0)), "r"(__float_as_uint(a1)),
          "r"(__float_as_uint(a2)), "r"(__float_as_uint(a3)),
          "r"(__float_as_uint(b0)), "r"(__float_as_uint(b1)));
}

// pack W[64][128] -> Apk fragment layout: Apk[kstep(16)][m16tile(4)][lane(32)][4]
__device__ __forceinline__ void packA(float* Apk, const float* __restrict__ w, int tid) {
    int kg = (tid & 31) * 4;
    int mb = (tid >> 5) * 8;
#pragma unroll
    for (int mm = 0; mm < 8; mm++) {
        int m = mb + mm;
        float4 v = *(const float4*)(w + m * 128 + kg);
        float vv[4] = {v.x, v.y, v.z, v.w};
#pragma unroll
        for (int i = 0; i < 4; i++) {
            int k = kg + i;
            int s = k >> 3, kin = k & 7;
            int tg = kin & 3, sub = kin >> 2;
            int mw2 = m >> 4, mloc = m & 15;
            int j = sub * 2 + (mloc >> 3);
            int ln2 = (mloc & 7) * 4 + tg;
            Apk[((s * 4 + mw2) * 32 + ln2) * 4 + j] = totf32(vv[i]);
        }
    }
}

// stage W[64][128] -> Ws[128][WSS] (conv_low fp32 path)
__device__ __forceinline__ void stageW(float* Ws, const float* __restrict__ w, int tid) {
    int kg = (tid & 31) * 4;
    int mb = (tid >> 5) * 8;
#pragma unroll
    for (int mm = 0; mm < 8; mm++) {
        int m = mb + mm;
        float4 v = *(const float4*)(w + m * 128 + kg);
        Ws[(kg + 0) * WSS + m] = v.x;
        Ws[(kg + 1) * WSS + m] = v.y;
        Ws[(kg + 2) * WSS + m] = v.z;
        Ws[(kg + 3) * WSS + m] = v.w;
    }
}

// mainloop over one K=16 chunk (proven fp32) — conv_low
__device__ __forceinline__ void mm16(const float* WsK, const float* Xs,
                                     int tm, int tn, u64 acc[4][8]) {
#pragma unroll
    for (int k = 0; k < 16; k++) {
        const float* wp = WsK + k * WSS + tm * 8;
        u64 a0 = *(const u64*)(wp);
        u64 a1 = *(const u64*)(wp + 2);
        u64 a2 = *(const u64*)(wp + 4);
        u64 a3 = *(const u64*)(wp + 6);
        float4 xl = *(const float4*)(Xs + k * 256 + tn * 4);
        float4 xh = *(const float4*)(Xs + k * 256 + 128 + tn * 4);
        u64 a[4] = {a0, a1, a2, a3};
        u64 b[8] = {pk2(xl.x, xl.x), pk2(xl.y, xl.y), pk2(xl.z, xl.z), pk2(xl.w, xl.w),
                    pk2(xh.x, xh.x), pk2(xh.y, xh.y), pk2(xh.z, xh.z), pk2(xh.w, xh.w)};
#pragma unroll
        for (int i = 0; i < 4; i++)
#pragma unroll
            for (int j = 0; j < 8; j++) acc[i][j] = ffma2(a[i], b[j], acc[i][j]);
    }
}

constexpr int XCH = 16 * 256;   // floats per chunk buffer (conv_low)

// ---------------- RPN: tf32 mma conv 128->64 + fused heads ----------------
constexpr int XSTR = 264;               // X row stride (banks 8*tig+gid: conflict-free)
constexpr int XCR  = 16 * XSTR;         // 4224 floats per chunk
constexpr int HST  = 264;               // Hs row stride
constexpr int RPN_FLOATS = 8192 + 4 * XCR + 1344 + 24 + 64;
constexpr int RPN_SMEM = RPN_FLOATS * 4;   // ~106 KB
__global__ __launch_bounds__(256) void k_rpn2m(
    const float* __restrict__ comb2,
    const float* __restrict__ w_rpn, const float* __restrict__ b_rpn,
    const float* __restrict__ w_rlog, const float* __restrict__ b_rlog,
    const float* __restrict__ w_rdel, const float* __restrict__ b_rdel,
    float* __restrict__ out)
{
    extern __shared__ float sm[];
    float* Apk   = sm;                        // 8192
    float* Xb    = sm + 8192;                 // 4*XCR
    float* wc    = sm + 8192 + 4 * XCR;       // 1344
    float* bc    = wc + 1344;                 // 24
    float* biasS = bc + 24;                   // 64
    float* Hs    = sm;                        // reuse [0, 64*HST) after mainloop
    int tid = threadIdx.x;
    int lane = tid & 31, w = tid >> 5;
    int gid = lane >> 2, tig = lane & 3;
    int mwarp = w & 1, nw = (w >> 1) * 64;
    int vox0 = blockIdx.x * 256;
    int c4 = tid & 63, rg = tid >> 6;
    uint32_t sX = (uint32_t)__cvta_generic_to_shared(Xb);

    auto stage = [&](int kc) {
        uint32_t sbuf = sX + (kc & 3) * XCR * 4;
#pragma unroll
        for (int rr = 0; rr < 4; rr++) {
            int row = rg * 4 + rr;
            cpa16(sbuf + (row * XSTR + c4 * 4) * 4,
                  comb2 + (long long)(kc * 16 + row) * NV2 + vox0 + c4 * 4);
        }
        cp_commit();
    };

    stage(0); stage(1); stage(2);
    packA(Apk, w_rpn, tid);
    for (int i = tid; i < 64 * 21; i += 256) {
        int o = i / 21, t = i - o * 21;
        wc[i] = (t < 3) ? w_rlog[t * 64 + o] : w_rdel[(t - 3) * 64 + o];
    }
    if (tid < 21) bc[tid] = (tid < 3) ? b_rlog[tid] : b_rdel[tid - 3];
    if (tid < 64) biasS[tid] = b_rpn[tid];
    __syncthreads();

    float acc0[8][4], acc1[8][4];
#pragma unroll
    for (int t = 0; t < 8; t++)
#pragma unroll
        for (int j = 0; j < 4; j++) { acc0[t][j] = 0.f; acc1[t][j] = 0.f; }

#pragma unroll 1
    for (int kc = 0; kc < 8; kc++) {
        cp_wait_tail(kc);
        __syncthreads();
        if (kc + 3 < 8) stage(kc + 3);
        const float* Xc = Xb + (kc & 3) * XCR;
#pragma unroll
        for (int ks = 0; ks < 2; ks++) {
            int s = kc * 2 + ks;
            float4 av0 = *(const float4*)&Apk[((s * 4 + mwarp * 2 + 0) * 32 + lane) * 4];
            float4 av1 = *(const float4*)&Apk[((s * 4 + mwarp * 2 + 1) * 32 + lane) * 4];
            const float* xk = Xc + ks * 8 * XSTR + nw + gid;
#pragma unroll
            for (int t = 0; t < 8; t++) {
                float b0 = totf32(xk[tig * XSTR + t * 8]);
                float b1 = totf32(xk[(tig + 4) * XSTR + t * 8]);
                mma_tf32(acc0[t], av0.x, av0.y, av0.z, av0.w, b0, b1);
                mma_tf32(acc1[t], av1.x, av1.y, av1.z, av1.w, b0, b1);
            }
        }
    }
    __syncthreads();   // Apk/Xb dead; Hs overwrites

    int r0 = mwarp * 32 + gid;
    float br0 = biasS[r0], br1 = biasS[r0 + 8], br2 = biasS[r0 + 16], br3 = biasS[r0 + 24];
#pragma unroll
    for (int t = 0; t < 8; t++) {
        int col = nw + t * 8 + tig * 2;
        *(float2*)&Hs[r0 * HST + col] =
            make_float2(fmaxf(acc0[t][0] + br0, 0.f), fmaxf(acc0[t][1] + br0, 0.f));
        *(float2*)&Hs[(r0 + 8) * HST + col] =
            make_float2(fmaxf(acc0[t][2] + br1, 0.f), fmaxf(acc0[t][3] + br1, 0.f));
        *(float2*)&Hs[(r0 + 16) * HST + col] =
            make_float2(fmaxf(acc1[t][0] + br2, 0.f), fmaxf(acc1[t][1] + br2, 0.f));
        *(float2*)&Hs[(r0 + 24) * HST + col] =
            make_float2(fmaxf(acc1[t][2] + br3, 0.f), fmaxf(acc1[t][3] + br3, 0.f));
    }
    __syncthreads();

    int vx = tid;
    float a[21];
#pragma unroll
    for (int t = 0; t < 21; t++) a[t] = bc[t];
    for (int o = 0; o < 64; o++) {
        float h = Hs[o * HST + vx];
#pragma unroll
        for (int t = 0; t < 21; t++) a[t] = fmaf(wc[o * 21 + t], h, a[t]);
    }
    long long vox = vox0 + vx;
#pragma unroll
    for (int t = 0; t < 3; t++) out[vox * 3 + t] = a[t];
#pragma unroll
    for (int t = 0; t < 18; t++) out[(long long)NV2 * 3 + vox * 18 + t] = a[3 + t];
}

// ---------------- conv_low: up2 conv at 12^3 (4-stage ring, 4B cp.async) ----------------
constexpr int CL_FLOATS = 8448 + 4 * XCH + 64;
constexpr int CL_SMEM = CL_FLOATS * 4;
__global__ __launch_bounds__(256, 2) void k_conv_low2(
    const float* __restrict__ comb2, const int* __restrict__ props,
    const float* __restrict__ w_up2, const float* __restrict__ b_up2)
{
    extern __shared__ float sm[];
    float* Ws = sm; float* Xb = sm + 8448; float* sb = sm + 8448 + 4 * XCH;
    int tid = threadIdx.x;
    int p = blockIdx.y, n0 = blockIdx.x * 256;

    int tn = tid & 31, tm = tid >> 5;
    int c4 = tid & 63, rg = tid >> 6;
    int v4 = n0 + c4 * 4; if (v4 > V4 - 4) v4 = V4 - 4;
    int z0 = props[p * 7 + 1] >> 2, y0 = props[p * 7 + 2] >> 2, x0 = props[p * 7 + 3] >> 2;
    int d = v4 / 144; int r = v4 - d * 144; int hh = r / 12; int ww = r - hh * 12;
    long long base = (long long)(z0 + d) * 4096 + (y0 + hh) * 64 + (x0 + ww);
    uint32_t sX = (uint32_t)__cvta_generic_to_shared(Xb);

    auto stage = [&](int kc) {
        uint32_t sbuf = sX + (kc & 3) * XCH * 4;
#pragma unroll
        for (int rr = 0; rr < 4; rr++) {
            int row = rg * 4 + rr;
            const float* gp = comb2 + (long long)(kc * 16 + row) * NV2 + base;
            uint32_t ds = sbuf + (row * 256 + c4 * 4) * 4;
            cpa4(ds, gp); cpa4(ds + 4, gp + 1); cpa4(ds + 8, gp + 2); cpa4(ds + 12, gp + 3);
        }
        cp_commit();
    };

    stage(0); stage(1); stage(2);
    stageW(Ws, w_up2, tid);
    if (tid < 64) sb[tid] = b_up2[tid];
    __syncthreads();

    u64 acc[4][8];
#pragma unroll
    for (int i = 0; i < 4; i++) { int m = tm * 8 + 2 * i;
#pragma unroll
        for (int j = 0; j < 8; j++) acc[i][j] = pk2(sb[m], sb[m + 1]); }

#pragma unroll 1
    for (int kc = 0; kc < 8; kc++) {
        cp_wait_tail(kc);
        __syncthreads();
        if (kc + 3 < 8) stage(kc + 3);
        mm16(Ws + kc * 16 * WSS, Xb + (kc & 3) * XCH, tm, tn, acc);
    }

    float* Tb = g_T + (long long)(p * 64) * V4 + n0 + tn * 4;
#pragma unroll
    for (int i = 0; i < 4; i++) {
        int m = tm * 8 + 2 * i;
#pragma unroll
        for (int h = 0; h < 2; h++) {
            int n = n0 + h * 128 + tn * 4;
            if (n < V4) {
                float2 v0 = unpk2(acc[i][h * 4 + 0]), v1 = unpk2(acc[i][h * 4 + 1]);
                float2 v2 = unpk2(acc[i][h * 4 + 2]), v3 = unpk2(acc[i][h * 4 + 3]);
                *(float4*)(Tb + (long long)m * V4 + h * 128) = make_float4(v0.x, v1.x, v2.x, v3.x);
                *(float4*)(Tb + (long long)(m + 1) * V4 + h * 128) = make_float4(v0.y, v1.y, v2.y, v3.y);
            }
        }
    }
}

// ---------------- upsample 12->24 + instnorm + relu ----------------
__global__ __launch_bounds__(288) void k_upsample(
    const float* __restrict__ gam, const float* __restrict__ bet)
{
    int c = blockIdx.x, p = blockIdx.y;
    __shared__ float t[V4];
    __shared__ int   llo[24], lhi[24];
    __shared__ float lf[24];
    __shared__ float bs[9], bss[9];
    __shared__ float sA, sB;
    int tid = threadIdx.x;
    const float* tp = &g_T[(p * 64 + c) * V4];
    for (int i = tid; i < V4; i += 288) t[i] = tp[i];
    if (tid < 24) {
        int nd = tid * 11; int lo = nd / 23;
        llo[tid] = lo; lhi[tid] = min(lo + 1, 11);
        lf[tid] = (float)(nd - lo * 23) * (1.0f / 23.0f);
    }
    __syncthreads();

    float s = 0.f, ss = 0.f;
    float outv[2][24];
#pragma unroll
    for (int rep = 0; rep < 2; rep++) {
        int rrow = tid + rep * 288;
        int d = rrow / 24; int h = rrow - d * 24;
        int ld = llo[d], hd = lhi[d]; float fd = lf[d];
        int lh = llo[h], hh = lhi[h]; float fh = lf[h];
        const float* p00 = t + ld * 144 + lh * 12;
        const float* p01 = t + ld * 144 + hh * 12;
        const float* p10 = t + hd * 144 + lh * 12;
        const float* p11 = t + hd * 144 + hh * 12;
        float rowc[12];
#pragma unroll
        for (int i = 0; i < 12; i++) {
            float a0 = p00[i], a1 = p01[i], b0 = p10[i], b1 = p11[i];
            float a = a0 + (a1 - a0) * fh;
            float b = b0 + (b1 - b0) * fh;
            rowc[i] = a + (b - a) * fd;
        }
#pragma unroll
        for (int w = 0; w < 24; w++) {
            const int nw = w * 11;
            const int lw = nw / 23;
            const int hw = (lw + 1 < 11) ? lw + 1 : 11;
            const float fw = (float)(nw - lw * 23) * (1.0f / 23.0f);
            float v = rowc[lw] + (rowc[hw] - rowc[lw]) * fw;
            outv[rep][w] = v;
            s += v; ss = fmaf(v, v, ss);
        }
    }

#pragma unroll
    for (int off = 16; off; off >>= 1) {
        s  += __shfl_down_sync(0xffffffffu, s,  off);
        ss += __shfl_down_sync(0xffffffffu, ss, off);
    }
    int wrp = tid >> 5, ln = tid & 31;
    if (ln == 0) { bs[wrp] = s; bss[wrp] = ss; }
    __syncthreads();
    if (wrp == 0 && ln < 9) {
        s = bs[ln]; ss = bss[ln];
#pragma unroll
        for (int off = 8; off; off >>= 1) {
            s  += __shfl_down_sync(0x1ffu, s,  off);
            ss += __shfl_down_sync(0x1ffu, ss, off);
        }
        if (ln == 0) {
            float mean = s * (1.f / Vc);
            float var = ss * (1.f / Vc) - mean * mean;
            float a = gam[c] * rsqrtf(var + EPSN);
            sA = a; sB = bet[c] - mean * a;
        }
    }
    __syncthreads();
    float a = sA, b = sB;

    float* up = &g_U[((long long)(p * 64 + c)) * Vc];
#pragma unroll
    for (int rep = 0; rep < 2; rep++) {
        int rrow = tid + rep * 288;
        float* o = up + rrow * 24;
#pragma unroll
        for (int q = 0; q < 6; q++) {
            float v0 = fmaxf(fmaf(outv[rep][q*4+0], a, b), 0.f);
            float v1 = fmaxf(fmaf(outv[rep][q*4+1], a, b), 0.f);
            float v2 = fmaxf(fmaf(outv[rep][q*4+2], a, b), 0.f);
            float v3 = fmaxf(fmaf(outv[rep][q*4+3], a, b), 0.f);
            *(float4*)(o + q * 4) = make_float4(v0, v1, v2, v3);
        }
    }
}

// ---------------- back2: tf32 mma.sync GEMM (R15 proven), M64 x N128 per block ----------------
constexpr int WST = 68;
constexpr int XST = 132;
constexpr int XCB = 16 * XST;
constexpr int B2_FLOATS = 128 * WST + 4 * XCB + 64 + 128;
constexpr int B2_SMEM = B2_FLOATS * 4;
__global__ __launch_bounds__(256) void k_back2m(
    const float* __restrict__ out1, const int* __restrict__ props,
    const float* __restrict__ w_back2, const float* __restrict__ b_back2)
{
    extern __shared__ float sm[];
    float* Ws    = sm;
    float* Xb    = sm + 128 * WST;
    float* biasS = sm + 128 * WST + 4 * XCB;
    float* stS   = biasS + 64;
    int tid = threadIdx.x;
    int lane = tid & 31, w = tid >> 5;
    int gid = lane >> 2, tig = lane & 3;
    int mw = (w & 3) * 16, nw = (w >> 2) * 64;
    int p = blockIdx.y, n0 = blockIdx.x * 128;

    int tn = tid & 31, rg = tid >> 5;
    int v4 = n0 + tn * 4;
    int z0 = props[p * 7 + 1] >> 1, y0 = props[p * 7 + 2] >> 1, x0 = props[p * 7 + 3] >> 1;
    int d = v4 / 576; int r = v4 - d * 576; int hh = r / 24; int ww = r - hh * 24;
    long long o1b = ((long long)(z0 + d) * 128 + (y0 + hh)) * 128 + (x0 + ww);
    const float* Ub = g_U + ((long long)p * 64) * Vc + v4;
    uint32_t sX = (uint32_t)__cvta_generic_to_shared(Xb);

    auto stage = [&](int kc) {
        uint32_t sbuf = sX + (kc & 3) * XCB * 4;
        if (kc < 4) {
#pragma unroll
            for (int rr = 0; rr < 2; rr++) {
                int row = rg * 2 + rr;
                cpa16(sbuf + (row * XST + tn * 4) * 4, Ub + (long long)(kc * 16 + row) * Vc);
            }
        } else {
#pragma unroll
            for (int rr = 0; rr < 2; rr++) {
                int row = rg * 2 + rr;
                const float* gp = out1 + (long long)((kc - 4) * 16 + row) * C1STRIDE + o1b;
                uint32_t ds = sbuf + (row * XST + tn * 4) * 4;
                cpa8(ds, gp); cpa8(ds + 8, gp + 2);
            }
        }
        cp_commit();
    };

    stage(0); stage(1); stage(2);
    {
        int kg = (tid & 31) * 4;
        int mb = (tid >> 5) * 8;
#pragma unroll
        for (int mm = 0; mm < 8; mm++) {
            int m = mb + mm;
            float4 v = *(const float4*)(w_back2 + m * 128 + kg);
            Ws[(kg + 0) * WST + m] = totf32(v.x);
            Ws[(kg + 1) * WST + m] = totf32(v.y);
            Ws[(kg + 2) * WST + m] = totf32(v.z);
            Ws[(kg + 3) * WST + m] = totf32(v.w);
        }
    }
    if (tid < 64) biasS[tid] = b_back2[tid];
    __syncthreads();

    float acc[8][4];
#pragma unroll
    for (int t = 0; t < 8; t++)
#pragma unroll
        for (int j = 0; j < 4; j++) acc[t][j] = 0.f;

#pragma unroll 1
    for (int kc = 0; kc < 8; kc++) {
        cp_wait_tail(kc);
        __syncthreads();
        if (kc + 3 < 8) stage(kc + 3);
        const float* Wc = Ws + kc * 16 * WST;
        const float* Xc = Xb + (kc & 3) * XCB;
#pragma unroll
        for (int ks = 0; ks < 2; ks++) {
            const float* wk = Wc + ks * 8 * WST + mw + gid;
            float a0 = wk[tig * WST];
            float a1 = wk[tig * WST + 8];
            float a2 = wk[(tig + 4) * WST];
            float a3 = wk[(tig + 4) * WST + 8];
            const float* xk = Xc + ks * 8 * XST + nw + gid;
#pragma unroll
            for (int t = 0; t < 8; t++) {
                float b0 = totf32(xk[tig * XST + t * 8]);
                float b1 = totf32(xk[(tig + 4) * XST + t * 8]);
                mma_tf32(acc[t], a0, a1, a2, a3, b0, b1);
            }
        }
    }

    int r0 = mw + gid, r1 = mw + gid + 8;
    float bias0 = biasS[r0], bias1 = biasS[r1];
    float S0 = 0.f, Q0 = 0.f, S1 = 0.f, Q1 = 0.f;
    float* F0 = g_F + ((long long)(p * 64 + r0)) * Vc + n0 + nw + tig * 2;
    float* F1 = g_F + ((long long)(p * 64 + r1)) * Vc + n0 + nw + tig * 2;
#pragma unroll
    for (int t = 0; t < 8; t++) {
        float v00 = acc[t][0] + bias0, v01 = acc[t][1] + bias0;
        float v10 = acc[t][2] + bias1, v11 = acc[t][3] + bias1;
        *(float2*)(F0 + t * 8) = make_float2(v00, v01);
        *(float2*)(F1 + t * 8) = make_float2(v10, v11);
        S0 += v00 + v01; Q0 = fmaf(v00, v00, Q0); Q0 = fmaf(v01, v01, Q0);
        S1 += v10 + v11; Q1 = fmaf(v10, v10, Q1); Q1 = fmaf(v11, v11, Q1);
    }
#pragma unroll
    for (int off = 2; off; off >>= 1) {
        S0 += __shfl_down_sync(0xffffffffu, S0, off, 4);
        Q0 += __shfl_down_sync(0xffffffffu, Q0, off, 4);
        S1 += __shfl_down_sync(0xffffffffu, S1, off, 4);
        Q1 += __shfl_down_sync(0xffffffffu, Q1, off, 4);
    }
    if (tig == 0) {
        int half = w >> 2;
        stS[half * 64 + r0] = S0;  stS[half * 64 + r1] = S1;
    }
    __syncthreads();
    float sumv = 0.f;
    if (tid < 64) sumv = stS[tid] + stS[64 + tid];
    __syncthreads();
    if (tig == 0) {
        int half = w >> 2;
        stS[half * 64 + r0] = Q0;  stS[half * 64 + r1] = Q1;
    }
    __syncthreads();
    if (tid < 64) {
        int pbase = (p * NB2 + blockIdx.x) * 64;
        g_spS[pbase + tid] = sumv;
        g_spQ[pbase + tid] = stS[tid] + stS[64 + tid];
    }
}

// ---------------- normalize + relu + 3^3 maxpool (stats from partials) ----------------
__global__ __launch_bounds__(512) void k_pool(
    const float* __restrict__ gam, const float* __restrict__ bet)
{
    int o = blockIdx.x, p = blockIdx.y;
    __shared__ float sS, sQ;
    if (threadIdx.x < 32) {
        float S = 0.f, Q = 0.f;
        for (int b2 = threadIdx.x; b2 < NB2; b2 += 32) {
            S += g_spS[(p * NB2 + b2) * 64 + o];
            Q += g_spQ[(p * NB2 + b2) * 64 + o];
        }
#pragma unroll
        for (int off = 16; off; off >>= 1) {
            S += __shfl_down_sync(0xffffffffu, S, off);
            Q += __shfl_down_sync(0xffffffffu, Q, off);
        }
        if (threadIdx.x == 0) { sS = S; sQ = Q; }
    }
    __syncthreads();
    float mean = sS * (1.f / Vc);
    float var = sQ * (1.f / Vc) - mean * mean;
    float a = gam[o] * rsqrtf(var + EPSN);
    float b = bet[o] - mean * a;

    int j = threadIdx.x;
    int od = j >> 6; int r = j & 63; int oh = r >> 3; int ow = r & 7;
    const float* Fp = &g_F[((long long)(p * 64 + o)) * Vc];
    float m = -1e30f;
#pragma unroll
    for (int dz = 0; dz < 3; dz++)
#pragma unroll
        for (int dy = 0; dy < 3; dy++)
#pragma unroll
            for (int dx = 0; dx < 3; dx++) {
                float v = Fp[(od * 3 + dz) * 576 + (oh * 3 + dy) * 24 + (ow * 3 + dx)];
                m = fmaxf(m, fmaxf(fmaf(v, a, b), 0.f));
            }
    g_CR[(p * 64 + o) * 512 + j] = m;
}

// ---------------- fc1 GEMM (K-split, cp.async double-buffered) ----------------
constexpr int WS2 = 68;
constexpr int FC1_FLOATS = 2 * 64 * WS2 + 2 * 64 * 65;
constexpr int FC1_SMEM = FC1_FLOATS * 4;
__global__ __launch_bounds__(256) void k_fc1(const float* __restrict__ w_fc1)
{
    extern __shared__ float sm[];
    float* Wb0 = sm;
    float* Wb1 = sm + 64 * WS2;
    float* Xb0 = sm + 2 * 64 * WS2;
    float* Xb1 = Xb0 + 64 * 65;
    int tid = threadIdx.x;
    int m0 = blockIdx.x * 64;
    int kb = blockIdx.y;
    int tp = tid & 63, tm = tid >> 6;
    uint32_t sW0 = (uint32_t)__cvta_generic_to_shared(Wb0);
    uint32_t sW1 = (uint32_t)__cvta_generic_to_shared(Wb1);
    uint32_t sXb0 = (uint32_t)__cvta_generic_to_shared(Xb0);
    uint32_t sXb1 = (uint32_t)__cvta_generic_to_shared(Xb1);

    int wrow = tid >> 2, wc4 = tid & 3;

    auto stage = [&](int ch) {
        int buf = ch & 1;
        int k0 = kb * 2048 + ch * 64;
        const float* gw = w_fc1 + (long long)(m0 + wrow) * 32768 + k0 + wc4 * 16;
        uint32_t dw = (buf ? sW1 : sW0) + (wrow * WS2 + wc4 * 16) * 4;
        cpa16(dw, gw); cpa16(dw + 16, gw + 4); cpa16(dw + 32, gw + 8); cpa16(dw + 48, gw + 12);
        uint32_t sXd = buf ? sXb1 : sXb0;
#pragma unroll
        for (int it = 0; it < 16; it++) {
            int idx = tid + it * 256;
            int kk = idx & 63, row = idx >> 6;
            cpa4(sXd + (kk * 65 + row) * 4, g_CR + row * 32768 + k0 + kk);
        }
        cp_commit();
    };

    float acc[16];
#pragma unroll
    for (int i = 0; i < 16; i++) acc[i] = 0.f;

    stage(0);
#pragma unroll 1
    for (int ch = 0; ch < 32; ch++) {
        if (ch < 31) { stage(ch + 1); cp_wait<1>(); }
        else cp_wait<0>();
        __syncthreads();
        const float* Wsb = (ch & 1) ? Wb1 : Wb0;
        const float* Xsb = (ch & 1) ? Xb1 : Xb0;
#pragma unroll 8
        for (int k = 0; k < 64; k++) {
            float xv = Xsb[k * 65 + tp];
#pragma unroll
            for (int i = 0; i < 16; i++) acc[i] = fmaf(Wsb[(tm * 16 + i) * WS2 + k], xv, acc[i]);
        }
        __syncthreads();
    }
    float* outp = &g_X1p[((long long)kb * 64 + tp) * 512 + m0 + tm * 16];
#pragma unroll
    for (int i = 0; i < 16; i++) outp[i] = acc[i];
}

// ---------------- fc1 reduce + fc2 + relu + rcnn heads (fused) ----------------
__global__ __launch_bounds__(256) void k_fc2h(
    const float* __restrict__ b_fc1,
    const float* __restrict__ w_fc2, const float* __restrict__ b_fc2,
    const float* __restrict__ w_logit, const float* __restrict__ b_logit,
    const float* __restrict__ w_delta, const float* __restrict__ b_delta,
    float* __restrict__ out)
{
    int p = blockIdx.x; int o = threadIdx.x;
    __shared__ float xs[512];
    __shared__ float x2[256];
    for (int m = o; m < 512; m += 256) {
        float s = b_fc1[m];
#pragma unroll
        for (int kb = 0; kb < 16; kb++) s += g_X1p[((long long)kb * 64 + p) * 512 + m];
        xs[m] = fmaxf(s, 0.f);
    }
    __syncthreads();
    const float* wp = &w_fc2[o * 512];
    float s = b_fc2[o];
#pragma unroll 8
    for (int k = 0; k < 512; k++) s = fmaf(wp[k], xs[k], s);
    x2[o] = fmaxf(s, 0.f);
    __syncthreads();

    int w = o >> 5, ln = o & 31;
    const long long offL = (long long)NV2 * 21;
    for (int t = w; t < 14; t += 8) {
        const float* wt = (t < 2) ? &w_logit[t * 256] : &w_delta[(t - 2) * 256];
        float sv = 0.f;
        for (int k = ln; k < 256; k += 32) sv = fmaf(wt[k], x2[k], sv);
#pragma unroll
        for (int off = 16; off; off >>= 1) sv += __shfl_down_sync(0xffffffffu, sv, off);
        if (ln == 0) {
            if (t < 2) out[offL + p * 2 + t] = sv + b_logit[t];
            else       out[offL + 128 + p * 12 + (t - 2)] = sv + b_delta[t - 2];
        }
    }
}

// ---------------- launch ----------------
extern "C" void kernel_launch(void* const* d_in, const int* in_sizes, int n_in,
                              void* d_out, int out_size)
{
    const float* out1    = (const float*)d_in[0];
    const float* comb2   = (const float*)d_in[1];
    const int*   props   = (const int*)  d_in[2];
    const float* w_rpn   = (const float*)d_in[3];  const float* b_rpn   = (const float*)d_in[4];
    const float* w_rlog  = (const float*)d_in[5];  const float* b_rlog  = (const float*)d_in[6];
    const float* w_rdel  = (const float*)d_in[7];  const float* b_rdel  = (const float*)d_in[8];
    const float* w_up2   = (const float*)d_in[9];  const float* b_up2   = (const float*)d_in[10];
    const float* gu_up2  = (const float*)d_in[11]; const float* be_up2  = (const float*)d_in[12];
    const float* w_back2 = (const float*)d_in[13]; const float* b_back2 = (const float*)d_in[14];
    const float* gu_bk2  = (const float*)d_in[15]; const float* be_bk2  = (const float*)d_in[16];
    const float* w_fc1   = (const float*)d_in[17]; const float* b_fc1   = (const float*)d_in[18];
    const float* w_fc2   = (const float*)d_in[19]; const float* b_fc2   = (const float*)d_in[20];
    const float* w_logit = (const float*)d_in[21]; const float* b_logit = (const float*)d_in[22];
    const float* w_delta = (const float*)d_in[23]; const float* b_delta = (const float*)d_in[24];
    float* out = (float*)d_out;

    cudaFuncSetAttribute(k_rpn2m, cudaFuncAttributeMaxDynamicSharedMemorySize, RPN_SMEM);
    cudaFuncSetAttribute(k_conv_low2, cudaFuncAttributeMaxDynamicSharedMemorySize, CL_SMEM);
    cudaFuncSetAttribute(k_back2m, cudaFuncAttributeMaxDynamicSharedMemorySize, B2_SMEM);
    cudaFuncSetAttribute(k_fc1, cudaFuncAttributeMaxDynamicSharedMemorySize, FC1_SMEM);

    k_rpn2m<<<512, 256, RPN_SMEM>>>(comb2, w_rpn, b_rpn, w_rlog, b_rlog, w_rdel, b_rdel, out);
    k_conv_low2<<<dim3(7, P_), 256, CL_SMEM>>>(comb2, props, w_up2, b_up2);
    k_upsample<<<dim3(64, P_), 288>>>(gu_up2, be_up2);
    k_back2m<<<dim3(NB2, P_), 256, B2_SMEM>>>(out1, props, w_back2, b_back2);
    k_pool<<<dim3(64, P_), 512>>>(gu_bk2, be_bk2);
    k_fc1<<<dim3(8, 16), 256, FC1_SMEM>>>(w_fc1);
    k_fc2h<<<P_, 256>>>(b_fc1, w_fc2, b_fc2, w_logit, b_logit, w_delta, b_delta, out);
}